// round 2
// baseline (speedup 1.0000x reference)
#include <cuda_runtime.h>
#include <math.h>

#define N_NODES 50000
#define D 100
#define E_EDGES 800000
#define OUTD 300

// Scratch (allocation-free): ping-pong feature buffers + CSR + per-node score.
__device__ __align__(16) float g_feats[2][(size_t)N_NODES * D];
__device__ __align__(16) float g_nr[128];
__device__ float g_score[N_NODES];
__device__ int g_rowptr[N_NODES + 1];

// ---------------------------------------------------------------------------
// Normalize none_relation (one block).
__global__ void nr_kernel(const float* __restrict__ none_rel) {
    __shared__ float ssum[128];
    int t = threadIdx.x;
    float v = (t < D) ? none_rel[t] : 0.f;
    ssum[t] = v * v;
    __syncthreads();
    for (int s = 64; s > 0; s >>= 1) {
        if (t < s) ssum[t] += ssum[t + s];
        __syncthreads();
    }
    float inv = 1.f / fmaxf(sqrtf(ssum[0]), 1e-12f);
    g_nr[t] = (t < D) ? v * inv : 0.f;
}

// ---------------------------------------------------------------------------
// CSR row pointers via binary search (rows are sorted). adj is int32 pairs.
__global__ void rowptr_kernel(const int* __restrict__ adj) {
    int r = blockIdx.x * blockDim.x + threadIdx.x;
    if (r > N_NODES) return;
    int lo = 0, hi = E_EDGES;
    while (lo < hi) {
        int mid = (lo + hi) >> 1;
        int rv = adj[2 * mid];
        if (rv < r) lo = mid + 1; else hi = mid;
    }
    g_rowptr[r] = lo;
}

// ---------------------------------------------------------------------------
// feats0 = tanh(features); write to scratch buf 0 and out columns [0, D).
__global__ void tanh_kernel(const float* __restrict__ feat, float* __restrict__ out) {
    int i = blockIdx.x * blockDim.x + threadIdx.x;
    if (i >= N_NODES * D) return;
    float v = tanhf(feat[i]);
    g_feats[0][i] = v;
    int n = i / D;
    int d = i - n * D;
    out[(size_t)n * OUTD + d] = v;
}

// ---------------------------------------------------------------------------
// Per-node score: s[c] = -dot(feats[c], nr) / max(||feats[c]||, eps).
// One warp per node; lanes 0..24 each own a float4 chunk (25*4 = 100).
__global__ void score_kernel(int buf) {
    int warp = (blockIdx.x * blockDim.x + threadIdx.x) >> 5;
    int lane = threadIdx.x & 31;
    if (warp >= N_NODES) return;
    const float* f = g_feats[buf] + (size_t)warp * D;
    float dot = 0.f, ss = 0.f;
    if (lane < 25) {
        float4 fv = *(const float4*)(f + lane * 4);
        float4 nv = *(const float4*)(g_nr + lane * 4);
        dot = fv.x * nv.x + fv.y * nv.y + fv.z * nv.z + fv.w * nv.w;
        ss  = fv.x * fv.x + fv.y * fv.y + fv.z * fv.z + fv.w * fv.w;
    }
    #pragma unroll
    for (int o = 16; o; o >>= 1) {
        dot += __shfl_xor_sync(0xffffffffu, dot, o);
        ss  += __shfl_xor_sync(0xffffffffu, ss, o);
    }
    if (lane == 0)
        g_score[warp] = -dot / fmaxf(sqrtf(ss), 1e-12f);
}

// ---------------------------------------------------------------------------
// Softmax attention + weighted gather per row. One warp per row.
__global__ void row_kernel(const int* __restrict__ adj, int buf,
                           float* __restrict__ out, int outoff) {
    int warp = (blockIdx.x * blockDim.x + threadIdx.x) >> 5;
    int lane = threadIdx.x & 31;
    if (warp >= N_NODES) return;
    int beg = g_rowptr[warp];
    int end = g_rowptr[warp + 1];
    const float* __restrict__ fin = g_feats[buf];

    // max over edge scores
    float m = -3.402823466e38f;
    for (int e = beg + lane; e < end; e += 32) {
        int c = adj[2 * e + 1];
        m = fmaxf(m, g_score[c]);
    }
    #pragma unroll
    for (int o = 16; o; o >>= 1)
        m = fmaxf(m, __shfl_xor_sync(0xffffffffu, m, o));

    // softmax denom
    float den = 0.f;
    for (int e = beg + lane; e < end; e += 32) {
        int c = adj[2 * e + 1];
        den += __expf(g_score[c] - m);
    }
    #pragma unroll
    for (int o = 16; o; o >>= 1)
        den += __shfl_xor_sync(0xffffffffu, den, o);

    // weighted accumulate (unrolled x2 for MLP)
    float4 acc = make_float4(0.f, 0.f, 0.f, 0.f);
    int e = beg;
    for (; e + 1 < end; e += 2) {
        int c0 = adj[2 * e + 1];
        int c1 = adj[2 * e + 3];
        float w0 = __expf(g_score[c0] - m);
        float w1 = __expf(g_score[c1] - m);
        if (lane < 25) {
            float4 f0 = *(const float4*)(fin + (size_t)c0 * D + lane * 4);
            float4 f1 = *(const float4*)(fin + (size_t)c1 * D + lane * 4);
            acc.x += w0 * f0.x + w1 * f1.x;
            acc.y += w0 * f0.y + w1 * f1.y;
            acc.z += w0 * f0.z + w1 * f1.z;
            acc.w += w0 * f0.w + w1 * f1.w;
        }
    }
    if (e < end) {
        int c0 = adj[2 * e + 1];
        float w0 = __expf(g_score[c0] - m);
        if (lane < 25) {
            float4 f0 = *(const float4*)(fin + (size_t)c0 * D + lane * 4);
            acc.x += w0 * f0.x;
            acc.y += w0 * f0.y;
            acc.z += w0 * f0.z;
            acc.w += w0 * f0.w;
        }
    }

    float inv = (end > beg) ? (1.f / den) : 0.f;
    if (lane < 25) {
        float4 r;
        r.x = tanhf(acc.x * inv);
        r.y = tanhf(acc.y * inv);
        r.z = tanhf(acc.z * inv);
        r.w = tanhf(acc.w * inv);
        *(float4*)(g_feats[buf ^ 1] + (size_t)warp * D + lane * 4) = r;
        *(float4*)(out + (size_t)warp * OUTD + outoff + lane * 4) = r;
    }
}

// ---------------------------------------------------------------------------
extern "C" void kernel_launch(void* const* d_in, const int* in_sizes, int n_in,
                              void* d_out, int out_size) {
    const float* features = (const float*)d_in[0];
    // d_in[1] = rel_emb: unused by the reference computation.
    const int* adj        = (const int*)d_in[2];   // int32 pairs (JAX demotes int64)
    const float* none_rel = (const float*)d_in[3];
    float* out = (float*)d_out;

    nr_kernel<<<1, 128>>>(none_rel);
    rowptr_kernel<<<(N_NODES + 1 + 255) / 256, 256>>>(adj);
    tanh_kernel<<<(N_NODES * D + 255) / 256, 256>>>(features, out);

    int buf = 0;
    for (int depth = 0; depth < 2; ++depth) {
        score_kernel<<<(N_NODES * 32 + 255) / 256, 256>>>(buf);
        row_kernel<<<(N_NODES * 32 + 255) / 256, 256>>>(adj, buf, out, D * (depth + 1));
        buf ^= 1;
    }
}

// round 4
// speedup vs baseline: 1.2565x; 1.2565x over previous
#include <cuda_runtime.h>
#include <math.h>

#define N_NODES 50000
#define D 100
#define E_EDGES 800000
#define OUTD 300

// Scratch (allocation-free): ping-pong feature buffers + ping-pong weights +
// CSR row pointers. w[c] = exp(score[c]); score in [-1,1] so no overflow and
// the reference's max-subtraction is mathematically a no-op for the ratio.
__device__ __align__(16) float g_feats[2][(size_t)N_NODES * D];
__device__ __align__(16) float g_nr[128];
__device__ float g_w[2][N_NODES];
__device__ int g_rowptr[N_NODES + 1];

// ---------------------------------------------------------------------------
// Normalize none_relation (one block).
__global__ void nr_kernel(const float* __restrict__ none_rel) {
    __shared__ float ssum[128];
    int t = threadIdx.x;
    float v = (t < D) ? none_rel[t] : 0.f;
    ssum[t] = v * v;
    __syncthreads();
    for (int s = 64; s > 0; s >>= 1) {
        if (t < s) ssum[t] += ssum[t + s];
        __syncthreads();
    }
    float inv = 1.f / fmaxf(sqrtf(ssum[0]), 1e-12f);
    g_nr[t] = (t < D) ? v * inv : 0.f;
}

// ---------------------------------------------------------------------------
// CSR row pointers via binary search (rows are sorted). adj is int32 pairs.
__global__ void rowptr_kernel(const int* __restrict__ adj) {
    int r = blockIdx.x * blockDim.x + threadIdx.x;
    if (r > N_NODES) return;
    int lo = 0, hi = E_EDGES;
    while (lo < hi) {
        int mid = (lo + hi) >> 1;
        if (adj[2 * mid] < r) lo = mid + 1; else hi = mid;
    }
    g_rowptr[r] = lo;
}

// ---------------------------------------------------------------------------
// Warp-collective epilogue: given this node's new feature chunk (f4, valid on
// lanes 0..24), compute w = exp(-dot(l2norm(f), nr)) into g_w[wbuf].
__device__ __forceinline__ void score_epilogue(float4 f4, int lane, int node, int wbuf) {
    float dot = 0.f, ss = 0.f;
    if (lane < 25) {
        float4 nv = *(const float4*)(g_nr + lane * 4);
        dot = f4.x * nv.x + f4.y * nv.y + f4.z * nv.z + f4.w * nv.w;
        ss  = f4.x * f4.x + f4.y * f4.y + f4.z * f4.z + f4.w * f4.w;
    }
    #pragma unroll
    for (int o = 16; o; o >>= 1) {
        dot += __shfl_xor_sync(0xffffffffu, dot, o);
        ss  += __shfl_xor_sync(0xffffffffu, ss, o);
    }
    if (lane == 0)
        g_w[wbuf][node] = __expf(-dot / fmaxf(sqrtf(ss), 1e-12f));
}

// ---------------------------------------------------------------------------
// feats0 = tanh(features) (warp per node) + fused score epilogue into g_w[0].
__global__ void tanh_score_kernel(const float* __restrict__ feat,
                                  float* __restrict__ out) {
    int node = (blockIdx.x * blockDim.x + threadIdx.x) >> 5;
    int lane = threadIdx.x & 31;
    if (node >= N_NODES) return;
    float4 r = make_float4(0.f, 0.f, 0.f, 0.f);
    if (lane < 25) {
        float4 v = *(const float4*)(feat + (size_t)node * D + lane * 4);
        r.x = tanhf(v.x); r.y = tanhf(v.y); r.z = tanhf(v.z); r.w = tanhf(v.w);
        *(float4*)(g_feats[0] + (size_t)node * D + lane * 4) = r;
        *(float4*)(out + (size_t)node * OUTD + lane * 4) = r;
    }
    score_epilogue(r, lane, node, 0);
}

// ---------------------------------------------------------------------------
// Single-pass attention row kernel. One warp per row.
// Reads feats[buf] and w[buf]; LAST=false writes feats[buf^1] and w[buf^1].
template <bool LAST>
__global__ void row_kernel(const int* __restrict__ adj, int buf,
                           float* __restrict__ out, int outoff) {
    int row = (blockIdx.x * blockDim.x + threadIdx.x) >> 5;
    int lane = threadIdx.x & 31;
    if (row >= N_NODES) return;
    int beg = g_rowptr[row];
    int end = g_rowptr[row + 1];
    const float* __restrict__ fin = g_feats[buf];
    const float* __restrict__ win = g_w[buf];

    float4 acc = make_float4(0.f, 0.f, 0.f, 0.f);
    float den = 0.f;
    int e = beg;
    for (; e + 1 < end; e += 2) {
        int c0 = adj[2 * e + 1];
        int c1 = adj[2 * e + 3];
        float w0 = win[c0];
        float w1 = win[c1];
        den += w0 + w1;
        if (lane < 25) {
            float4 f0 = *(const float4*)(fin + (size_t)c0 * D + lane * 4);
            float4 f1 = *(const float4*)(fin + (size_t)c1 * D + lane * 4);
            acc.x += w0 * f0.x + w1 * f1.x;
            acc.y += w0 * f0.y + w1 * f1.y;
            acc.z += w0 * f0.z + w1 * f1.z;
            acc.w += w0 * f0.w + w1 * f1.w;
        }
    }
    if (e < end) {
        int c0 = adj[2 * e + 1];
        float w0 = win[c0];
        den += w0;
        if (lane < 25) {
            float4 f0 = *(const float4*)(fin + (size_t)c0 * D + lane * 4);
            acc.x += w0 * f0.x;
            acc.y += w0 * f0.y;
            acc.z += w0 * f0.z;
            acc.w += w0 * f0.w;
        }
    }

    float inv = (end > beg) ? (1.f / den) : 0.f;
    float4 r = make_float4(0.f, 0.f, 0.f, 0.f);
    if (lane < 25) {
        r.x = tanhf(acc.x * inv);
        r.y = tanhf(acc.y * inv);
        r.z = tanhf(acc.z * inv);
        r.w = tanhf(acc.w * inv);
        *(float4*)(out + (size_t)row * OUTD + outoff + lane * 4) = r;
        if (!LAST)
            *(float4*)(g_feats[buf ^ 1] + (size_t)row * D + lane * 4) = r;
    }
    if (!LAST)
        score_epilogue(r, lane, row, buf ^ 1);
}

// ---------------------------------------------------------------------------
extern "C" void kernel_launch(void* const* d_in, const int* in_sizes, int n_in,
                              void* d_out, int out_size) {
    const float* features = (const float*)d_in[0];
    // d_in[1] = rel_emb: unused by the reference computation.
    const int* adj        = (const int*)d_in[2];   // int32 pairs (JAX demotes int64)
    const float* none_rel = (const float*)d_in[3];
    float* out = (float*)d_out;

    const int WPB = 256;
    const int NODE_BLOCKS = (N_NODES * 32 + WPB - 1) / WPB;

    nr_kernel<<<1, 128>>>(none_rel);
    rowptr_kernel<<<(N_NODES + 1 + 255) / 256, 256>>>(adj);
    tanh_score_kernel<<<NODE_BLOCKS, WPB>>>(features, out);
    row_kernel<false><<<NODE_BLOCKS, WPB>>>(adj, 0, out, D);
    row_kernel<true ><<<NODE_BLOCKS, WPB>>>(adj, 1, out, 2 * D);
}

// round 5
// speedup vs baseline: 1.3131x; 1.0451x over previous
#include <cuda_runtime.h>
#include <cuda_fp16.h>
#include <math.h>

#define N_NODES 50000
#define D 100
#define E_EDGES 800000
#define OUTD 300

// Scratch (allocation-free). Gathered features live in fp16 (post-tanh values
// are in [-1,1]; quantization err ~2^-12 rel, far under the 1e-3 threshold).
// Softmax weights w[c] = exp(score[c]) are computed from fp32 registers.
// score in [-1,1] so exp never overflows => max-subtraction is a no-op.
__device__ __align__(16) __half g_hf[2][(size_t)N_NODES * D];
__device__ __align__(16) float g_nr[128];
__device__ float g_w[2][N_NODES];
__device__ int g_rowptr[N_NODES + 1];

// ---------------------------------------------------------------------------
__global__ void nr_kernel(const float* __restrict__ none_rel) {
    __shared__ float ssum[128];
    int t = threadIdx.x;
    float v = (t < D) ? none_rel[t] : 0.f;
    ssum[t] = v * v;
    __syncthreads();
    for (int s = 64; s > 0; s >>= 1) {
        if (t < s) ssum[t] += ssum[t + s];
        __syncthreads();
    }
    float inv = 1.f / fmaxf(sqrtf(ssum[0]), 1e-12f);
    g_nr[t] = (t < D) ? v * inv : 0.f;
}

// ---------------------------------------------------------------------------
// CSR row pointers via binary search (rows sorted). adj is int32 pairs.
__global__ void rowptr_kernel(const int* __restrict__ adj) {
    int r = blockIdx.x * blockDim.x + threadIdx.x;
    if (r > N_NODES) return;
    int lo = 0, hi = E_EDGES;
    while (lo < hi) {
        int mid = (lo + hi) >> 1;
        if (adj[2 * mid] < r) lo = mid + 1; else hi = mid;
    }
    g_rowptr[r] = lo;
}

// ---------------------------------------------------------------------------
// Warp-collective: from fp32 feature chunk (lanes 0..24), compute
// w = exp(-dot(l2norm(f), nr)) into g_w[wbuf], and store fp16 feats.
__device__ __forceinline__ void epilogue_store(float4 r, int lane, int node,
                                               int fbuf, int wbuf) {
    if (lane < 25) {
        __half2 lo = __floats2half2_rn(r.x, r.y);
        __half2 hi = __floats2half2_rn(r.z, r.w);
        uint2 pack;
        pack.x = *(unsigned int*)&lo;
        pack.y = *(unsigned int*)&hi;
        *(uint2*)(g_hf[fbuf] + (size_t)node * D + lane * 4) = pack;
    }
    float dot = 0.f, ss = 0.f;
    if (lane < 25) {
        float4 nv = *(const float4*)(g_nr + lane * 4);
        dot = r.x * nv.x + r.y * nv.y + r.z * nv.z + r.w * nv.w;
        ss  = r.x * r.x + r.y * r.y + r.z * r.z + r.w * r.w;
    }
    #pragma unroll
    for (int o = 16; o; o >>= 1) {
        dot += __shfl_xor_sync(0xffffffffu, dot, o);
        ss  += __shfl_xor_sync(0xffffffffu, ss, o);
    }
    if (lane == 0)
        g_w[wbuf][node] = __expf(-dot / fmaxf(sqrtf(ss), 1e-12f));
}

// ---------------------------------------------------------------------------
// feats0 = tanh(features): fp32 to out cols [0,D), fp16 to scratch, w to g_w[0].
__global__ void tanh_score_kernel(const float* __restrict__ feat,
                                  float* __restrict__ out) {
    int node = (blockIdx.x * blockDim.x + threadIdx.x) >> 5;
    int lane = threadIdx.x & 31;
    if (node >= N_NODES) return;
    float4 r = make_float4(0.f, 0.f, 0.f, 0.f);
    if (lane < 25) {
        float4 v = *(const float4*)(feat + (size_t)node * D + lane * 4);
        r.x = tanhf(v.x); r.y = tanhf(v.y); r.z = tanhf(v.z); r.w = tanhf(v.w);
        *(float4*)(out + (size_t)node * OUTD + lane * 4) = r;
    }
    epilogue_store(r, lane, node, 0, 0);
}

// ---------------------------------------------------------------------------
// Single-pass attention row kernel, fp16 gathers, edge loop unrolled x4.
__device__ __forceinline__ void fma_edge(float4& acc, float w,
                                         const __half* __restrict__ fin,
                                         int c, int lane) {
    uint2 raw = *(const uint2*)(fin + (size_t)c * D + lane * 4);
    float2 lo = __half22float2(*(__half2*)&raw.x);
    float2 hi = __half22float2(*(__half2*)&raw.y);
    acc.x += w * lo.x;
    acc.y += w * lo.y;
    acc.z += w * hi.x;
    acc.w += w * hi.y;
}

template <bool LAST>
__global__ void row_kernel(const int* __restrict__ adj, int buf,
                           float* __restrict__ out, int outoff) {
    int row = (blockIdx.x * blockDim.x + threadIdx.x) >> 5;
    int lane = threadIdx.x & 31;
    if (row >= N_NODES) return;
    int beg = g_rowptr[row];
    int end = g_rowptr[row + 1];
    const __half* __restrict__ fin = g_hf[buf];
    const float* __restrict__ win = g_w[buf];

    float4 acc = make_float4(0.f, 0.f, 0.f, 0.f);
    float den = 0.f;
    int e = beg;
    int n4 = beg + ((end - beg) & ~3);
    for (; e < n4; e += 4) {
        int c0 = adj[2 * e + 1];
        int c1 = adj[2 * e + 3];
        int c2 = adj[2 * e + 5];
        int c3 = adj[2 * e + 7];
        float w0 = win[c0], w1 = win[c1], w2 = win[c2], w3 = win[c3];
        den += (w0 + w1) + (w2 + w3);
        if (lane < 25) {
            fma_edge(acc, w0, fin, c0, lane);
            fma_edge(acc, w1, fin, c1, lane);
            fma_edge(acc, w2, fin, c2, lane);
            fma_edge(acc, w3, fin, c3, lane);
        }
    }
    for (; e < end; ++e) {
        int c0 = adj[2 * e + 1];
        float w0 = win[c0];
        den += w0;
        if (lane < 25)
            fma_edge(acc, w0, fin, c0, lane);
    }

    float inv = (end > beg) ? (1.f / den) : 0.f;
    float4 r = make_float4(0.f, 0.f, 0.f, 0.f);
    if (lane < 25) {
        r.x = tanhf(acc.x * inv);
        r.y = tanhf(acc.y * inv);
        r.z = tanhf(acc.z * inv);
        r.w = tanhf(acc.w * inv);
        *(float4*)(out + (size_t)row * OUTD + outoff + lane * 4) = r;
    }
    if (!LAST)
        epilogue_store(r, lane, row, buf ^ 1, buf ^ 1);
}

// ---------------------------------------------------------------------------
extern "C" void kernel_launch(void* const* d_in, const int* in_sizes, int n_in,
                              void* d_out, int out_size) {
    const float* features = (const float*)d_in[0];
    // d_in[1] = rel_emb: unused by the reference computation.
    const int* adj        = (const int*)d_in[2];   // int32 pairs (JAX demotes int64)
    const float* none_rel = (const float*)d_in[3];
    float* out = (float*)d_out;

    const int WPB = 256;
    const int NODE_BLOCKS = (N_NODES * 32 + WPB - 1) / WPB;

    nr_kernel<<<1, 128>>>(none_rel);
    rowptr_kernel<<<(N_NODES + 1 + 255) / 256, 256>>>(adj);
    tanh_score_kernel<<<NODE_BLOCKS, WPB>>>(features, out);
    row_kernel<false><<<NODE_BLOCKS, WPB>>>(adj, 0, out, D);
    row_kernel<true ><<<NODE_BLOCKS, WPB>>>(adj, 1, out, 2 * D);
}

// round 6
// speedup vs baseline: 1.3468x; 1.0257x over previous
#include <cuda_runtime.h>
#include <math.h>

#define N_NODES 50000
#define D 100
#define DP 104                 // padded row: 100 premultiplied feats + w + 3 pad
#define E_EDGES 800000
#define OUTD 300

// Scratch (allocation-free). g_gw[b][node*DP .. ] = [w*f[0..99], w, 0,0,0].
// w[c] = exp(score[c]); score in [-1,1] so exp never overflows and the
// reference's max-subtraction cancels exactly in the softmax ratio.
__device__ __align__(16) float g_gw[2][(size_t)N_NODES * DP];
__device__ __align__(16) float g_nr[128];
__device__ int g_coff[E_EDGES];        // col element-offset: col[e] * DP
__device__ int g_rowptr[N_NODES + 1];

// ---------------------------------------------------------------------------
__device__ __forceinline__ void fadd2(unsigned long long& a, unsigned long long b) {
    asm("add.rn.f32x2 %0, %0, %1;" : "+l"(a) : "l"(b));
}
__device__ __forceinline__ float2 unpack2(unsigned long long v) {
    float2 r;
    asm("mov.b64 {%0, %1}, %2;" : "=f"(r.x), "=f"(r.y) : "l"(v));
    return r;
}

// ---------------------------------------------------------------------------
__global__ void nr_kernel(const float* __restrict__ none_rel) {
    __shared__ float ssum[128];
    int t = threadIdx.x;
    float v = (t < D) ? none_rel[t] : 0.f;
    ssum[t] = v * v;
    __syncthreads();
    for (int s = 64; s > 0; s >>= 1) {
        if (t < s) ssum[t] += ssum[t + s];
        __syncthreads();
    }
    float inv = 1.f / fmaxf(sqrtf(ssum[0]), 1e-12f);
    g_nr[t] = (t < D) ? v * inv : 0.f;
}

// ---------------------------------------------------------------------------
// Prep: packed col offsets + CSR row pointers (rows sorted; binary search).
__global__ void prep_kernel(const int* __restrict__ adj) {
    int i = blockIdx.x * blockDim.x + threadIdx.x;
    if (i < E_EDGES)
        g_coff[i] = adj[2 * i + 1] * DP;
    if (i <= N_NODES) {
        int lo = 0, hi = E_EDGES;
        while (lo < hi) {
            int mid = (lo + hi) >> 1;
            if (adj[2 * mid] < i) lo = mid + 1; else hi = mid;
        }
        g_rowptr[i] = lo;
    }
}

// ---------------------------------------------------------------------------
// Warp-collective epilogue: from this node's fp32 feature chunk r (valid on
// lanes 0..24), compute w = exp(-dot(l2norm(r), nr)) and store the
// premultiplied row [w*r, w, 0,0,0] into g_gw[fbuf].
__device__ __forceinline__ void epilogue_store(float4 r, int lane, int node, int fbuf) {
    float dot = 0.f, ss = 0.f;
    if (lane < 25) {
        float4 nv = *(const float4*)(g_nr + lane * 4);
        dot = r.x * nv.x + r.y * nv.y + r.z * nv.z + r.w * nv.w;
        ss  = r.x * r.x + r.y * r.y + r.z * r.z + r.w * r.w;
    }
    #pragma unroll
    for (int o = 16; o; o >>= 1) {
        dot += __shfl_xor_sync(0xffffffffu, dot, o);
        ss  += __shfl_xor_sync(0xffffffffu, ss, o);
    }
    float w = __expf(-dot / fmaxf(sqrtf(ss), 1e-12f));
    w = __shfl_sync(0xffffffffu, w, 0);   // identical on all lanes; keep uniform
    if (lane < 26) {
        float4 s = (lane < 25)
            ? make_float4(w * r.x, w * r.y, w * r.z, w * r.w)
            : make_float4(w, 0.f, 0.f, 0.f);
        *(float4*)(g_gw[fbuf] + (size_t)node * DP + lane * 4) = s;
    }
}

// ---------------------------------------------------------------------------
// Layer 0: r = tanh(features); write out cols [0,D), build g_gw[0].
__global__ void tanh_score_kernel(const float* __restrict__ feat,
                                  float* __restrict__ out) {
    int node = (blockIdx.x * blockDim.x + threadIdx.x) >> 5;
    int lane = threadIdx.x & 31;
    if (node >= N_NODES) return;
    float4 r = make_float4(0.f, 0.f, 0.f, 0.f);
    if (lane < 25) {
        float4 v = *(const float4*)(feat + (size_t)node * D + lane * 4);
        r.x = tanhf(v.x); r.y = tanhf(v.y); r.z = tanhf(v.z); r.w = tanhf(v.w);
        *(float4*)(out + (size_t)node * OUTD + lane * 4) = r;
    }
    epilogue_store(r, lane, node, 0);
}

// ---------------------------------------------------------------------------
// Attention row kernel: pure gather-sum of premultiplied rows.
// acc (lanes 0..24) = sum_c w_c * f_c ; lane 25's acc.x = sum_c w_c = den.
template <bool LAST>
__global__ void row_kernel(int buf, float* __restrict__ out, int outoff) {
    int row = (blockIdx.x * blockDim.x + threadIdx.x) >> 5;
    int lane = threadIdx.x & 31;
    if (row >= N_NODES) return;
    int beg = g_rowptr[row];
    int end = g_rowptr[row + 1];
    const float* __restrict__ gwb = g_gw[buf];

    unsigned long long a0 = 0ull, a1 = 0ull;   // two f32x2 accumulators
    int laneoff = lane * 4;
    int e = beg;
    int n4 = beg + ((end - beg) & ~3);
    for (; e < n4; e += 4) {
        int o0 = g_coff[e];
        int o1 = g_coff[e + 1];
        int o2 = g_coff[e + 2];
        int o3 = g_coff[e + 3];
        if (lane < 26) {
            ulonglong2 v0 = *(const ulonglong2*)(gwb + o0 + laneoff);
            ulonglong2 v1 = *(const ulonglong2*)(gwb + o1 + laneoff);
            ulonglong2 v2 = *(const ulonglong2*)(gwb + o2 + laneoff);
            ulonglong2 v3 = *(const ulonglong2*)(gwb + o3 + laneoff);
            fadd2(a0, v0.x); fadd2(a1, v0.y);
            fadd2(a0, v1.x); fadd2(a1, v1.y);
            fadd2(a0, v2.x); fadd2(a1, v2.y);
            fadd2(a0, v3.x); fadd2(a1, v3.y);
        }
    }
    for (; e < end; ++e) {
        int o0 = g_coff[e];
        if (lane < 26) {
            ulonglong2 v0 = *(const ulonglong2*)(gwb + o0 + laneoff);
            fadd2(a0, v0.x); fadd2(a1, v0.y);
        }
    }

    float2 lo = unpack2(a0);
    float2 hi = unpack2(a1);
    float den = __shfl_sync(0xffffffffu, lo.x, 25);     // lane 25 accumulated w
    float inv = (end > beg) ? (1.f / den) : 0.f;

    float4 r = make_float4(0.f, 0.f, 0.f, 0.f);
    if (lane < 25) {
        r.x = tanhf(lo.x * inv);
        r.y = tanhf(lo.y * inv);
        r.z = tanhf(hi.x * inv);
        r.w = tanhf(hi.y * inv);
        *(float4*)(out + (size_t)row * OUTD + outoff + lane * 4) = r;
    }
    if (!LAST)
        epilogue_store(r, lane, row, buf ^ 1);
}

// ---------------------------------------------------------------------------
extern "C" void kernel_launch(void* const* d_in, const int* in_sizes, int n_in,
                              void* d_out, int out_size) {
    const float* features = (const float*)d_in[0];
    // d_in[1] = rel_emb: unused by the reference computation.
    const int* adj        = (const int*)d_in[2];   // int32 pairs (JAX demotes int64)
    const float* none_rel = (const float*)d_in[3];
    float* out = (float*)d_out;

    const int WPB = 256;
    const int NODE_BLOCKS = (N_NODES * 32 + WPB - 1) / WPB;

    nr_kernel<<<1, 128>>>(none_rel);
    prep_kernel<<<(E_EDGES + 255) / 256, 256>>>(adj);
    tanh_score_kernel<<<NODE_BLOCKS, WPB>>>(features, out);
    row_kernel<false><<<NODE_BLOCKS, WPB>>>(0, out, D);
    row_kernel<true ><<<NODE_BLOCKS, WPB>>>(1, out, 2 * D);
}

// round 8
// speedup vs baseline: 1.4196x; 1.0541x over previous
#include <cuda_runtime.h>
#include <math.h>

#define N_NODES 50000
#define D 100
#define DP 104                 // padded row: 100 premultiplied feats + w + 3 pad
#define E_EDGES 800000
#define OUTD 300

// Scratch (allocation-free). g_gw[b][node*DP..] = [w*f[0..99], w, 0,0,0].
// w[c] = exp(score[c]); score in [-1,1] so exp never overflows and the
// reference's max-subtraction cancels exactly in the softmax ratio.
__device__ __align__(16) float g_gw[2][(size_t)N_NODES * DP + 32];
__device__ __align__(16) float g_nr[128];
__device__ int g_coff[E_EDGES];
__device__ int g_rowptr[N_NODES + 1];

// ---------------------------------------------------------------------------
__device__ __forceinline__ void fadd2(unsigned long long& a, unsigned long long b) {
    asm("add.rn.f32x2 %0, %0, %1;" : "+l"(a) : "l"(b));
}
__device__ __forceinline__ float2 unpack2(unsigned long long v) {
    float2 r;
    asm("mov.b64 {%0, %1}, %2;" : "=f"(r.x), "=f"(r.y) : "l"(v));
    return r;
}
__device__ __forceinline__ float tanha(float x) {      // HW tanh approx
    float r;
    asm("tanh.approx.f32 %0, %1;" : "=f"(r) : "f"(x));
    return r;
}

// ---------------------------------------------------------------------------
__global__ void nr_kernel(const float* __restrict__ none_rel) {
    __shared__ float ssum[128];
    int t = threadIdx.x;
    float v = (t < D) ? none_rel[t] : 0.f;
    ssum[t] = v * v;
    __syncthreads();
    for (int s = 64; s > 0; s >>= 1) {
        if (t < s) ssum[t] += ssum[t + s];
        __syncthreads();
    }
    float inv = 1.f / fmaxf(sqrtf(ssum[0]), 1e-12f);
    g_nr[t] = (t < D) ? v * inv : 0.f;
}

// ---------------------------------------------------------------------------
// Prep: packed col offsets + CSR row pointers (rows sorted; binary search).
__global__ void prep_kernel(const int* __restrict__ adj) {
    int i = blockIdx.x * blockDim.x + threadIdx.x;
    if (i < E_EDGES)
        g_coff[i] = adj[2 * i + 1] * DP;
    if (i <= N_NODES) {
        int lo = 0, hi = E_EDGES;
        while (lo < hi) {
            int mid = (lo + hi) >> 1;
            if (adj[2 * mid] < i) lo = mid + 1; else hi = mid;
        }
        g_rowptr[i] = lo;
    }
}

// ---------------------------------------------------------------------------
// Warp-collective epilogue: from this node's fp32 feature chunk r (lanes 0..24),
// compute w = exp(-dot(l2norm(r), nr)); store [w*r, w, 0,0,0] into g_gw[fbuf].
__device__ __forceinline__ void epilogue_store(float4 r, int lane, int node, int fbuf) {
    float dot = 0.f, ss = 0.f;
    if (lane < 25) {
        float4 nv = *(const float4*)(g_nr + lane * 4);
        dot = r.x * nv.x + r.y * nv.y + r.z * nv.z + r.w * nv.w;
        ss  = r.x * r.x + r.y * r.y + r.z * r.z + r.w * r.w;
    }
    #pragma unroll
    for (int o = 16; o; o >>= 1) {
        dot += __shfl_xor_sync(0xffffffffu, dot, o);
        ss  += __shfl_xor_sync(0xffffffffu, ss, o);
    }
    float w = __expf(-dot / fmaxf(sqrtf(ss), 1e-12f));
    if (lane < 26) {
        float4 s = (lane < 25)
            ? make_float4(w * r.x, w * r.y, w * r.z, w * r.w)
            : make_float4(w, 0.f, 0.f, 0.f);
        *(float4*)(g_gw[fbuf] + (size_t)node * DP + lane * 4) = s;
    }
}

// ---------------------------------------------------------------------------
// Layer 0: r = tanh(features); write out cols [0,D), build g_gw[0].
__global__ void tanh_score_kernel(const float* __restrict__ feat,
                                  float* __restrict__ out) {
    int node = (blockIdx.x * blockDim.x + threadIdx.x) >> 5;
    int lane = threadIdx.x & 31;
    if (node >= N_NODES) return;
    float4 r = make_float4(0.f, 0.f, 0.f, 0.f);
    if (lane < 25) {
        float4 v = *(const float4*)(feat + (size_t)node * D + lane * 4);
        r.x = tanha(v.x); r.y = tanha(v.y); r.z = tanha(v.z); r.w = tanha(v.w);
        *(float4*)(out + (size_t)node * OUTD + lane * 4) = r;
    }
    epilogue_store(r, lane, node, 0);
}

// ---------------------------------------------------------------------------
// Attention row kernel: gather-sum of premultiplied rows, unroll x8 (MLP=8).
// Lanes 0..24 accumulate features; lane 25's first slot accumulates den.
template <bool LAST>
__global__ void __launch_bounds__(256) row_kernel(int buf, float* __restrict__ out,
                                                  int outoff) {
    int row = (blockIdx.x * blockDim.x + threadIdx.x) >> 5;
    int lane = threadIdx.x & 31;
    if (row >= N_NODES) return;
    int beg = g_rowptr[row];
    int end = g_rowptr[row + 1];
    const float* __restrict__ gwb = g_gw[buf];

    unsigned long long a0 = 0ull, a1 = 0ull, a2 = 0ull, a3 = 0ull;
    int laneoff = lane * 4;
    int e = beg;

    for (; e + 8 <= end; e += 8) {
        int o[8];
        #pragma unroll
        for (int j = 0; j < 8; ++j) o[j] = g_coff[e + j];
        if (lane < 26) {
            ulonglong2 v[8];
            #pragma unroll
            for (int j = 0; j < 8; ++j)
                v[j] = *(const ulonglong2*)(gwb + o[j] + laneoff);
            #pragma unroll
            for (int j = 0; j < 8; j += 2) {
                fadd2(a0, v[j].x);     fadd2(a1, v[j].y);
                fadd2(a2, v[j + 1].x); fadd2(a3, v[j + 1].y);
            }
        }
    }
    for (; e + 2 <= end; e += 2) {
        int o0 = g_coff[e];
        int o1 = g_coff[e + 1];
        if (lane < 26) {
            ulonglong2 v0 = *(const ulonglong2*)(gwb + o0 + laneoff);
            ulonglong2 v1 = *(const ulonglong2*)(gwb + o1 + laneoff);
            fadd2(a0, v0.x); fadd2(a1, v0.y);
            fadd2(a2, v1.x); fadd2(a3, v1.y);
        }
    }
    if (e < end) {
        int o0 = g_coff[e];
        if (lane < 26) {
            ulonglong2 v0 = *(const ulonglong2*)(gwb + o0 + laneoff);
            fadd2(a0, v0.x); fadd2(a1, v0.y);
        }
    }

    fadd2(a0, a2);
    fadd2(a1, a3);
    float2 lo = unpack2(a0);
    float2 hi = unpack2(a1);
    float den = __shfl_sync(0xffffffffu, lo.x, 25);     // lane 25 accumulated w
    float inv = (end > beg) ? (1.f / den) : 0.f;

    float4 r = make_float4(0.f, 0.f, 0.f, 0.f);
    if (lane < 25) {
        r.x = tanha(lo.x * inv);
        r.y = tanha(lo.y * inv);
        r.z = tanha(hi.x * inv);
        r.w = tanha(hi.y * inv);
        *(float4*)(out + (size_t)row * OUTD + outoff + lane * 4) = r;
    }
    if (!LAST)
        epilogue_store(r, lane, row, buf ^ 1);
}

// ---------------------------------------------------------------------------
extern "C" void kernel_launch(void* const* d_in, const int* in_sizes, int n_in,
                              void* d_out, int out_size) {
    const float* features = (const float*)d_in[0];
    // d_in[1] = rel_emb: unused by the reference computation.
    const int* adj        = (const int*)d_in[2];   // int32 pairs (JAX demotes int64)
    const float* none_rel = (const float*)d_in[3];
    float* out = (float*)d_out;

    const int WPB = 256;
    const int NODE_BLOCKS = (N_NODES * 32 + WPB - 1) / WPB;

    nr_kernel<<<1, 128>>>(none_rel);
    prep_kernel<<<(E_EDGES + 255) / 256, 256>>>(adj);
    tanh_score_kernel<<<NODE_BLOCKS, WPB>>>(features, out);
    row_kernel<false><<<NODE_BLOCKS, WPB>>>(0, out, D);
    row_kernel<true ><<<NODE_BLOCKS, WPB>>>(1, out, 2 * D);
}

// round 9
// speedup vs baseline: 1.4333x; 1.0096x over previous
#include <cuda_runtime.h>
#include <math.h>

#define N_NODES 50000
#define D 100
#define DP 104                 // padded row: 100 premultiplied feats + w + 3 pad
#define E_EDGES 800000
#define OUTD 300

// Scratch (allocation-free). g_gw[b][node*DP..] = [w*f[0..99], w, 0,0,0].
// w[c] = exp(score[c]); score in [-1,1] so exp never overflows and the
// reference's max-subtraction cancels exactly in the softmax ratio.
__device__ __align__(16) float g_gw[2][(size_t)N_NODES * DP + 32];
__device__ __align__(16) float g_nr[128];
__device__ int g_coff[E_EDGES];
__device__ int g_rowptr[N_NODES + 1];

// ---------------------------------------------------------------------------
__device__ __forceinline__ void fadd2(unsigned long long& a, unsigned long long b) {
    asm("add.rn.f32x2 %0, %0, %1;" : "+l"(a) : "l"(b));
}
__device__ __forceinline__ float2 unpack2(unsigned long long v) {
    float2 r;
    asm("mov.b64 {%0, %1}, %2;" : "=f"(r.x), "=f"(r.y) : "l"(v));
    return r;
}
__device__ __forceinline__ float tanha(float x) {      // HW tanh approx
    float r;
    asm("tanh.approx.f32 %0, %1;" : "=f"(r) : "f"(x));
    return r;
}

// ---------------------------------------------------------------------------
// Prep: packed col offsets + CSR row pointers (rows sorted; binary search).
// Block 0 threads 0..127 additionally build the normalized none_relation.
__global__ void prep_kernel(const int* __restrict__ adj,
                            const float* __restrict__ none_rel) {
    if (blockIdx.x == 0 && threadIdx.x < 128) {
        __shared__ float ssum[128];
        int t = threadIdx.x;
        float v = (t < D) ? none_rel[t] : 0.f;
        ssum[t] = v * v;
        __syncthreads();
        for (int s = 64; s > 0; s >>= 1) {
            if (t < s) ssum[t] += ssum[t + s];
            __syncthreads();
        }
        float inv = 1.f / fmaxf(sqrtf(ssum[0]), 1e-12f);
        g_nr[t] = (t < D) ? v * inv : 0.f;
    }
    int i = blockIdx.x * blockDim.x + threadIdx.x;
    if (i < E_EDGES)
        g_coff[i] = adj[2 * i + 1] * DP;
    if (i <= N_NODES) {
        int lo = 0, hi = E_EDGES;
        while (lo < hi) {
            int mid = (lo + hi) >> 1;
            if (adj[2 * mid] < i) lo = mid + 1; else hi = mid;
        }
        g_rowptr[i] = lo;
    }
}

// ---------------------------------------------------------------------------
// Warp-collective epilogue: from this node's fp32 feature chunk r (lanes 0..24),
// compute w = exp(-dot(l2norm(r), nr)); store [w*r, w, 0,0,0] into g_gw[fbuf].
__device__ __forceinline__ void epilogue_store(float4 r, int lane, int node, int fbuf) {
    float dot = 0.f, ss = 0.f;
    if (lane < 25) {
        float4 nv = *(const float4*)(g_nr + lane * 4);
        dot = r.x * nv.x + r.y * nv.y + r.z * nv.z + r.w * nv.w;
        ss  = r.x * r.x + r.y * r.y + r.z * r.z + r.w * r.w;
    }
    #pragma unroll
    for (int o = 16; o; o >>= 1) {
        dot += __shfl_xor_sync(0xffffffffu, dot, o);
        ss  += __shfl_xor_sync(0xffffffffu, ss, o);
    }
    float w = __expf(-dot / fmaxf(sqrtf(ss), 1e-12f));
    if (lane < 26) {
        float4 s = (lane < 25)
            ? make_float4(w * r.x, w * r.y, w * r.z, w * r.w)
            : make_float4(w, 0.f, 0.f, 0.f);
        *(float4*)(g_gw[fbuf] + (size_t)node * DP + lane * 4) = s;
    }
}

// ---------------------------------------------------------------------------
// Layer 0: r = tanh(features); write out cols [0,D), build g_gw[0].
__global__ void tanh_score_kernel(const float* __restrict__ feat,
                                  float* __restrict__ out) {
    int node = (blockIdx.x * blockDim.x + threadIdx.x) >> 5;
    int lane = threadIdx.x & 31;
    if (node >= N_NODES) return;
    float4 r = make_float4(0.f, 0.f, 0.f, 0.f);
    if (lane < 25) {
        float4 v = *(const float4*)(feat + (size_t)node * D + lane * 4);
        r.x = tanha(v.x); r.y = tanha(v.y); r.z = tanha(v.z); r.w = tanha(v.w);
        *(float4*)(out + (size_t)node * OUTD + lane * 4) = r;
    }
    epilogue_store(r, lane, node, 0);
}

// ---------------------------------------------------------------------------
// Attention row kernel: gather-sum of premultiplied rows, unroll x16 (MLP=16).
// Lanes 0..24 accumulate features; lane 25's first slot accumulates den.
template <bool LAST>
__global__ void __launch_bounds__(256) row_kernel(int buf, float* __restrict__ out,
                                                  int outoff) {
    int row = (blockIdx.x * blockDim.x + threadIdx.x) >> 5;
    int lane = threadIdx.x & 31;
    if (row >= N_NODES) return;
    int beg = g_rowptr[row];
    int end = g_rowptr[row + 1];
    const float* __restrict__ gwb = g_gw[buf];

    unsigned long long a0 = 0ull, a1 = 0ull, a2 = 0ull, a3 = 0ull;
    int laneoff = lane * 4;
    int e = beg;

    // x16 batch: all 16 offsets then all 16 loads issued before consuming.
    for (; e + 16 <= end; e += 16) {
        int o[16];
        #pragma unroll
        for (int j = 0; j < 16; ++j) o[j] = g_coff[e + j];
        if (lane < 26) {
            ulonglong2 v[16];
            #pragma unroll
            for (int j = 0; j < 16; ++j)
                v[j] = *(const ulonglong2*)(gwb + o[j] + laneoff);
            #pragma unroll
            for (int j = 0; j < 16; j += 2) {
                fadd2(a0, v[j].x);     fadd2(a1, v[j].y);
                fadd2(a2, v[j + 1].x); fadd2(a3, v[j + 1].y);
            }
        }
    }
    for (; e + 4 <= end; e += 4) {
        int o[4];
        #pragma unroll
        for (int j = 0; j < 4; ++j) o[j] = g_coff[e + j];
        if (lane < 26) {
            ulonglong2 v[4];
            #pragma unroll
            for (int j = 0; j < 4; ++j)
                v[j] = *(const ulonglong2*)(gwb + o[j] + laneoff);
            fadd2(a0, v[0].x); fadd2(a1, v[0].y);
            fadd2(a2, v[1].x); fadd2(a3, v[1].y);
            fadd2(a0, v[2].x); fadd2(a1, v[2].y);
            fadd2(a2, v[3].x); fadd2(a3, v[3].y);
        }
    }
    for (; e < end; ++e) {
        int o0 = g_coff[e];
        if (lane < 26) {
            ulonglong2 v0 = *(const ulonglong2*)(gwb + o0 + laneoff);
            fadd2(a0, v0.x); fadd2(a1, v0.y);
        }
    }

    fadd2(a0, a2);
    fadd2(a1, a3);
    float2 lo = unpack2(a0);
    float2 hi = unpack2(a1);
    float den = __shfl_sync(0xffffffffu, lo.x, 25);     // lane 25 accumulated w
    float inv = (end > beg) ? (1.f / den) : 0.f;

    float4 r = make_float4(0.f, 0.f, 0.f, 0.f);
    if (lane < 25) {
        r.x = tanha(lo.x * inv);
        r.y = tanha(lo.y * inv);
        r.z = tanha(hi.x * inv);
        r.w = tanha(hi.y * inv);
        *(float4*)(out + (size_t)row * OUTD + outoff + lane * 4) = r;
    }
    if (!LAST)
        epilogue_store(r, lane, row, buf ^ 1);
}

// ---------------------------------------------------------------------------
extern "C" void kernel_launch(void* const* d_in, const int* in_sizes, int n_in,
                              void* d_out, int out_size) {
    const float* features = (const float*)d_in[0];
    // d_in[1] = rel_emb: unused by the reference computation.
    const int* adj        = (const int*)d_in[2];   // int32 pairs (JAX demotes int64)
    const float* none_rel = (const float*)d_in[3];
    float* out = (float*)d_out;

    const int WPB = 256;
    const int NODE_BLOCKS = (N_NODES * 32 + WPB - 1) / WPB;

    prep_kernel<<<(E_EDGES + 255) / 256, 256>>>(adj, none_rel);
    tanh_score_kernel<<<NODE_BLOCKS, WPB>>>(features, out);
    row_kernel<false><<<NODE_BLOCKS, WPB>>>(0, out, D);
    row_kernel<true ><<<NODE_BLOCKS, WPB>>>(1, out, 2 * D);
}